// round 1
// baseline (speedup 1.0000x reference)
#include <cuda_runtime.h>
#include <math.h>

// ---------------------------------------------------------------------------
// AcousticGuitarPoC: MLP params -> pre one-pole LP -> Karplus-Strong ->
// post one-pole LP -> 24-band 2-pole resonator body.
// B=8, N=32768, HOP=256 (all frame params are per-batch constants).
// ---------------------------------------------------------------------------

#define FS_F   44100.0f
#define PI_F   3.14159265358979323846f
#define NB     24
#define NSMP   32768
#define BATCH  8
#define LCH    128      // LP chunk length (threads=256 -> 256*128 = 32768)
#define NCH    256
#define BL     256      // body chunk length
#define BC     128      // body chunk count (128*256 = 32768)
#define KSL    768      // KS circular buffer length

struct KSParams {
    float m_pre, sc_pre, m_post, sc_post, g, s, fr;
    int   Di;
};

__device__ KSParams d_par[BATCH];
__device__ float  d_bA1[NB], d_bA2[NB], d_bB0[NB];
__device__ float  d_P[NB][4];                 // M^256 per band (2x2)
__device__ float  d_scr[BATCH * NSMP];        // stage scratch (1 MB)
__device__ float2 d_carry[BATCH][BC][NB];     // body zero-init chunk end states
__device__ float2 d_initS[BATCH][BC][NB];     // body corrected chunk init states

__device__ __forceinline__ float sigm(float x) { return 1.f / (1.f + expf(-x)); }
__device__ __forceinline__ float clampf(float x, float lo, float hi) {
    return fminf(fmaxf(x, lo), hi);
}

// ---------------------------------------------------------------------------
// Kernel 1: per-batch parameters, band coefficients, M^256, scalar outputs.
// ---------------------------------------------------------------------------
__global__ void param_kernel(const float* __restrict__ pitch,
                             const float* __restrict__ w1,
                             const float* __restrict__ b1,
                             const float* __restrict__ w2,
                             const float* __restrict__ b2,
                             const float* __restrict__ egain,
                             float* out_tail, int write_scalars)
{
    int tid = threadIdx.x;
    __shared__ float s_lc[BATCH], s_lm[BATCH], s_lp[BATCH];

    if (tid < BATCH) {
        float p = pitch[tid];
        float h[16];
        #pragma unroll
        for (int j = 0; j < 16; j++) h[j] = fmaxf(fmaf(p, w1[j], b1[j]), 0.f);
        float m0 = b2[0], m1 = b2[1], m2 = b2[2];
        #pragma unroll
        for (int j = 0; j < 16; j++) {
            m0 = fmaf(h[j], w2[0 * 16 + j], m0);
            m1 = fmaf(h[j], w2[1 * 16 + j], m1);
            m2 = fmaf(h[j], w2[2 * 16 + j], m2);
        }
        float lc = clampf(m0, -2.0f, 2.5f);
        float lm = clampf(m1, -2.5f, 0.0f);
        float lp = clampf(m2, -4.0f, 4.0f);
        s_lc[tid] = lc; s_lm[tid] = lm; s_lp[tid] = lp;

        KSParams P;
        P.g = 0.999f * sigm(lc);
        P.s = sigm(lm);

        float f0   = fmaxf(p, 60.f);
        float mult = clampf(2.f + 6.f * (f0 - 60.f) / 600.f, 2.f, 8.f);
        float cut  = fminf(2.f * PI_F * f0 * mult / FS_F, PI_F * 0.9f);
        float alpha = 1.f - expf(-cut);
        P.m_pre  = 1.f - alpha;           // y = m*y_prev + t
        P.sc_pre = alpha * egain[0];      // t = exc * gain * alpha

        float cutp = fminf(PI_F * sigm(lp), PI_F * 0.99f);
        float ap   = 1.f - expf(-cutp);
        P.m_post  = 1.f - ap;
        P.sc_post = ap;

        float D  = clampf(FS_F / f0, 2.f, 735.f);
        float Df = floorf(D);
        P.Di = (int)Df;
        P.fr = D - Df;
        d_par[tid] = P;
    }

    if (tid < NB) {
        double fc  = 80.0 * exp(log(100.0) * (double)tid / 23.0);
        float  fcf = (float)fc;
        float  w   = 2.f * PI_F * fcf / FS_F;
        float  r   = expf(-PI_F * fcf / (10.f * FS_F));
        float  a1  = -2.f * r * cosf(w);
        float  a2  = r * r;
        d_bA1[tid] = a1; d_bA2[tid] = a2; d_bB0[tid] = 1.f - r;
        // M = [[-a1,-a2],[1,0]];  P = M^256 via 8 squarings in double.
        double ma = -(double)a1, mb = -(double)a2, mc = 1.0, md = 0.0;
        for (int it = 0; it < 8; it++) {
            double na = ma * ma + mb * mc;
            double nb = ma * mb + mb * md;
            double nc = mc * ma + md * mc;
            double nd = mc * mb + md * md;
            ma = na; mb = nb; mc = nc; md = nd;
        }
        d_P[tid][0] = (float)ma; d_P[tid][1] = (float)mb;
        d_P[tid][2] = (float)mc; d_P[tid][3] = (float)md;
    }
    __syncthreads();

    if (tid == 0 && write_scalars) {
        float sc = 0.f, sm = 0.f, sp = 0.f;
        for (int b = 0; b < BATCH; b++) { sc += s_lc[b]; sm += s_lm[b]; sp += s_lp[b]; }
        out_tail[0] = sc / (float)BATCH;
        out_tail[1] = sm / (float)BATCH;
        out_tail[2] = sp / (float)BATCH;
    }
}

// ---------------------------------------------------------------------------
// Kernel 2/4: one-pole LP as chunked parallel scan. One block per batch,
// 256 threads x 128-sample chunks. stage 0: exc -> d_scr, stage 1: in-place.
// ---------------------------------------------------------------------------
__global__ void lp_kernel(const float* exc, int stage)
{
    int b = blockIdx.x, tid = threadIdx.x;
    KSParams P = d_par[b];
    float m  = (stage == 0) ? P.m_pre  : P.m_post;
    float sc = (stage == 0) ? P.sc_pre : P.sc_post;
    const float* x = ((stage == 0) ? exc : d_scr) + b * NSMP + tid * LCH;
    float* y = d_scr + b * NSMP + tid * LCH;

    // pass 1: zero-init chunk-end value
    float e = 0.f;
    #pragma unroll 8
    for (int k = 0; k < LCH; k++) e = fmaf(m, e, sc * x[k]);

    __shared__ float sh[NCH];
    sh[tid] = e;
    __syncthreads();

    float f = m;
    #pragma unroll
    for (int i = 0; i < 7; i++) f *= f;   // m^128

    // Hillis-Steele inclusive scan of y_end[c] = m^128 * y_end[c-1] + e[c]
    for (int ofs = 1; ofs < NCH; ofs <<= 1) {
        float v = (tid >= ofs) ? sh[tid - ofs] : 0.f;
        __syncthreads();
        sh[tid] = fmaf(f, v, sh[tid]);
        f *= f;
        __syncthreads();
    }

    // pass 2: recompute chunk with correct init, write output
    float yp = (tid > 0) ? sh[tid - 1] : 0.f;
    #pragma unroll 8
    for (int k = 0; k < LCH; k++) { yp = fmaf(m, yp, sc * x[k]); y[k] = yp; }
}

// ---------------------------------------------------------------------------
// Kernel 3: Karplus-Strong. One block per batch. Min delay Di >= 66, so
// chunks of min(blockDim, Di-2) samples are independent. Two barriers per
// chunk: read-all (old buffer) then write-all, which also makes the mod-768
// wraparound read (Di >= 511 case) race-free. In-place on d_scr.
// ---------------------------------------------------------------------------
__global__ void ks_kernel()
{
    int b = blockIdx.x, tid = threadIdx.x;
    KSParams P = d_par[b];
    __shared__ float buf[KSL];
    for (int i = tid; i < KSL; i += blockDim.x) buf[i] = 0.f;
    __syncthreads();

    int   Di  = P.Di;
    float fr  = P.fr;
    float w1f = 1.f - fr;
    float gs  = P.g * P.s;
    float g1s = P.g * (1.f - P.s);
    int Cb = min((int)blockDim.x, Di - 2);
    if (Cb < 1) Cb = 1;
    float* xio = d_scr + b * NSMP;

    for (int base = 0; base < NSMP; base += Cb) {
        int  n   = base + tid;
        bool act = (tid < Cb) && (n < NSMP);
        float y  = 0.f;
        if (act) {
            int i1 = (n - Di     + 2 * KSL) % KSL;
            int i2 = (n - Di - 1 + 2 * KSL) % KSL;
            int i3 = (n - Di - 2 + 2 * KSL) % KSL;
            float b1v = buf[i1], b2v = buf[i2], b3v = buf[i3];
            float z  = fmaf(fr, b2v, w1f * b1v);
            float z1 = fmaf(fr, b3v, w1f * b2v);
            y = xio[n] + fmaf(gs, z1, g1s * z);
        }
        __syncthreads();
        if (act) {
            buf[n % KSL] = y;
            xio[n] = y;
        }
        __syncthreads();
    }
}

// ---------------------------------------------------------------------------
// Kernel 5: body pass A — per (batch, chunk) block, lane = band.
// Zero-init serial 256-step 2-pole; store end state.
// ---------------------------------------------------------------------------
__global__ void bodyA_kernel()
{
    __shared__ float shx[BL];
    int b = blockIdx.y, c = blockIdx.x, tid = threadIdx.x;
    const float* x = d_scr + b * NSMP + c * BL;
    for (int i = tid; i < BL; i += 32) shx[i] = x[i];
    __syncthreads();
    if (tid < NB) {
        float a1 = d_bA1[tid], a2 = d_bA2[tid], b0 = d_bB0[tid];
        float y1 = 0.f, y2 = 0.f;
        #pragma unroll 8
        for (int t = 0; t < BL; t++) {
            float u = fmaf(-a2, y2, b0 * shx[t]);   // off critical path
            float y = fmaf(-a1, y1, u);
            y2 = y1; y1 = y;
        }
        d_carry[b][c][tid] = make_float2(y1, y2);
    }
}

// ---------------------------------------------------------------------------
// Kernel 6: body pass B — carry propagation: s_end[c] = M^256 s_end[c-1] + p[c].
// 192 threads = (batch, band) pairs; 128 sequential small matvecs.
// ---------------------------------------------------------------------------
__global__ void bodyB_kernel()
{
    int tid = threadIdx.x;
    if (tid >= BATCH * NB) return;
    int b = tid / NB, band = tid % NB;
    float p00 = d_P[band][0], p01 = d_P[band][1];
    float p10 = d_P[band][2], p11 = d_P[band][3];
    float s0 = 0.f, s1 = 0.f;
    for (int c = 0; c < BC; c++) {
        d_initS[b][c][band] = make_float2(s0, s1);
        float2 pc = d_carry[b][c][band];
        float n0 = fmaf(p00, s0, fmaf(p01, s1, pc.x));
        float n1 = fmaf(p10, s0, fmaf(p11, s1, pc.y));
        s0 = n0; s1 = n1;
    }
}

// ---------------------------------------------------------------------------
// Kernel 7: body pass C — recompute with correct init, weighted band sum.
// ---------------------------------------------------------------------------
__global__ void bodyC_kernel(const float* __restrict__ gains, float* __restrict__ out)
{
    __shared__ float shx[BL];
    __shared__ float tile[BL * 25];   // [t][band], stride 25 (pad)
    __shared__ float shg[NB];
    int b = blockIdx.y, c = blockIdx.x, tid = threadIdx.x;
    const float* x = d_scr + b * NSMP + c * BL;
    for (int i = tid; i < BL; i += 32) shx[i] = x[i];
    if (tid < NB) shg[tid] = gains[tid];
    __syncthreads();

    if (tid < NB) {
        float a1 = d_bA1[tid], a2 = d_bA2[tid], b0 = d_bB0[tid];
        float2 s = d_initS[b][c][tid];
        float y1 = s.x, y2 = s.y;
        #pragma unroll 8
        for (int t = 0; t < BL; t++) {
            float u = fmaf(-a2, y2, b0 * shx[t]);
            float y = fmaf(-a1, y1, u);
            tile[t * 25 + tid] = y;
            y2 = y1; y1 = y;
        }
    }
    __syncthreads();

    for (int t = tid; t < BL; t += 32) {
        float acc = 0.f;
        #pragma unroll
        for (int k = 0; k < NB; k++) acc = fmaf(tile[t * 25 + k], shg[k], acc);
        out[b * NSMP + c * BL + t] = acc;
    }
}

// ---------------------------------------------------------------------------
extern "C" void kernel_launch(void* const* d_in, const int* in_sizes, int n_in,
                              void* d_out, int out_size)
{
    const float* exc   = (const float*)d_in[0];   // [8,1,32768]
    const float* pitch = (const float*)d_in[1];   // [8,1]
    const float* w1    = (const float*)d_in[2];   // [16,1]
    const float* b1    = (const float*)d_in[3];   // [16]
    const float* w2    = (const float*)d_in[4];   // [3,16]
    const float* b2    = (const float*)d_in[5];   // [3]
    const float* eg    = (const float*)d_in[6];   // scalar
    const float* bg    = (const float*)d_in[7];   // [1,24]
    float* out = (float*)d_out;

    int wr = (out_size >= BATCH * NSMP + 3) ? 1 : 0;

    param_kernel<<<1, 32>>>(pitch, w1, b1, w2, b2, eg, out + BATCH * NSMP, wr);
    lp_kernel<<<BATCH, NCH>>>(exc, 0);            // pre LP -> d_scr
    ks_kernel<<<BATCH, 256>>>();                  // KS in-place
    lp_kernel<<<BATCH, NCH>>>(nullptr, 1);        // post LP in-place
    bodyA_kernel<<<dim3(BC, BATCH), 32>>>();
    bodyB_kernel<<<1, BATCH * NB>>>();
    bodyC_kernel<<<dim3(BC, BATCH), 32>>>(bg, out);
}

// round 3
// speedup vs baseline: 3.9228x; 3.9228x over previous
#include <cuda_runtime.h>
#include <math.h>

// ---------------------------------------------------------------------------
// AcousticGuitarPoC fused: MLP params + pre one-pole LP + Karplus-Strong +
// post one-pole LP in ONE kernel (whole signal resident in shared memory),
// then 3-pass parallel body resonator bank.
// B=8, N=32768. 4 kernel launches total.
// ---------------------------------------------------------------------------

#define FS_F   44100.0f
#define PI_F   3.14159265358979323846f
#define NB     24
#define NSMP   32768
#define BATCH  8
#define NTH    256      // fused-kernel threads
#define LCH    128      // LP chunk length (256*128 = 32768)
#define KSL    1024     // KS ring (power of 2; alias-free, see proof in ks loop)
#define BL     128      // body chunk length
#define BC     256      // body chunk count (256*128 = 32768)
#define NLVL   8        // log2(BC) scan levels

struct KSParams {
    float m_pre, sc_pre, m_post, sc_post, fr, gs, g1s;
    int   Di;
};

__device__ float  d_bA1[NB], d_bA2[NB], d_bB0[NB];
__device__ float  d_Pl[NB][NLVL][4];          // M^(BL*2^j), double-computed
__device__ float  d_scr[BATCH * NSMP];        // string output for body stage
__device__ float2 d_carry[BATCH][BC][NB];     // body zero-init chunk end states
__device__ float2 d_initS[BATCH][BC][NB];     // body corrected chunk init states

__device__ __forceinline__ float sigm(float x) { return 1.f / (1.f + expf(-x)); }
__device__ __forceinline__ float clampf(float x, float lo, float hi) {
    return fminf(fmaxf(x, lo), hi);
}

__device__ __forceinline__ void mlp_eval(float p,
    const float* __restrict__ w1, const float* __restrict__ b1,
    const float* __restrict__ w2, const float* __restrict__ b2,
    float& lc, float& lm, float& lp)
{
    float m0 = b2[0], m1 = b2[1], m2 = b2[2];
    #pragma unroll
    for (int j = 0; j < 16; j++) {
        float h = fmaxf(fmaf(p, w1[j], b1[j]), 0.f);
        m0 = fmaf(h, w2[j],      m0);
        m1 = fmaf(h, w2[16 + j], m1);
        m2 = fmaf(h, w2[32 + j], m2);
    }
    lc = clampf(m0, -2.0f, 2.5f);
    lm = clampf(m1, -2.5f, 0.0f);
    lp = clampf(m2, -4.0f, 4.0f);
}

// In-place one-pole LP over smem signal: y[n] = m*y[n-1] + sc*x[n].
// 256 threads, chunk = 128; chunked serial + Hillis-Steele carry scan.
__device__ void lp_inplace(float* sig, float* scanbuf, float m, float sc, int tid)
{
    float* x = sig + tid * LCH;

    float e = 0.f;
    #pragma unroll 8
    for (int k = 0; k < LCH; k++) e = fmaf(m, e, sc * x[k]);

    scanbuf[tid] = e;
    __syncthreads();

    float f = m;
    #pragma unroll
    for (int i = 0; i < 7; i++) f *= f;       // m^128

    #pragma unroll
    for (int ofs = 1; ofs < NTH; ofs <<= 1) {
        float v = (tid >= ofs) ? scanbuf[tid - ofs] : 0.f;
        __syncthreads();
        e = fmaf(f, v, e);
        scanbuf[tid] = e;
        f *= f;
        __syncthreads();
    }

    float yp = (tid > 0) ? scanbuf[tid - 1] : 0.f;
    #pragma unroll 8
    for (int k = 0; k < LCH; k++) { yp = fmaf(m, yp, sc * x[k]); x[k] = yp; }
    __syncthreads();
}

// ---------------------------------------------------------------------------
// Fused kernel: one block per batch. Signal lives in dynamic smem.
// ---------------------------------------------------------------------------
__global__ void fused_kernel(const float* __restrict__ exc,
                             const float* __restrict__ pitch,
                             const float* __restrict__ w1,
                             const float* __restrict__ b1,
                             const float* __restrict__ w2,
                             const float* __restrict__ b2,
                             const float* __restrict__ egain,
                             float* out_tail, int write_scalars)
{
    extern __shared__ float sm[];
    float* sig  = sm;              // [NSMP]
    float* buf  = sm + NSMP;       // [KSL]
    float* scan = buf + KSL;       // [NTH]

    __shared__ KSParams sp;
    __shared__ float s_lc[BATCH], s_lm[BATCH], s_lp[BATCH];
    int b = blockIdx.x, tid = threadIdx.x;

    if (tid == 0) {
        float p = pitch[b];
        float lc, lm, lp;
        mlp_eval(p, w1, b1, w2, b2, lc, lm, lp);

        KSParams P;
        float g = 0.999f * sigm(lc);
        float s = sigm(lm);
        P.gs  = g * s;
        P.g1s = g * (1.f - s);

        float f0    = fmaxf(p, 60.f);
        float mult  = clampf(2.f + 6.f * (f0 - 60.f) / 600.f, 2.f, 8.f);
        float cut   = fminf(2.f * PI_F * f0 * mult / FS_F, PI_F * 0.9f);
        float alpha = 1.f - expf(-cut);
        P.m_pre  = 1.f - alpha;
        P.sc_pre = alpha * egain[0];

        float cutp = fminf(PI_F * sigm(lp), PI_F * 0.99f);
        float ap   = 1.f - expf(-cutp);
        P.m_post  = 1.f - ap;
        P.sc_post = ap;

        float D  = clampf(FS_F / f0, 2.f, 735.f);
        float Df = floorf(D);
        P.Di = (int)Df;
        P.fr = D - Df;
        sp = P;
    }

    if (b == 0) {
        if (tid >= 32 && tid < 32 + BATCH) {
            int bb = tid - 32;
            mlp_eval(pitch[bb], w1, b1, w2, b2, s_lc[bb], s_lm[bb], s_lp[bb]);
        }
        if (tid >= 64 && tid < 64 + NB) {
            int band = tid - 64;
            double fc  = 80.0 * exp(log(100.0) * (double)band / 23.0);
            float  fcf = (float)fc;
            float  w   = 2.f * PI_F * fcf / FS_F;
            float  r   = expf(-PI_F * fcf / (10.f * FS_F));
            float  a1  = -2.f * r * cosf(w);
            float  a2  = r * r;
            d_bA1[band] = a1; d_bA2[band] = a2; d_bB0[band] = 1.f - r;
            // M = [[-a1,-a2],[1,0]]; all scan-level powers M^(128*2^j)
            // computed ENTIRELY in double (companion powers are non-normal,
            // float squaring loses ~2 digits via cancellation).
            double ma = -(double)a1, mb = -(double)a2, mc = 1.0, md = 0.0;
            for (int it = 0; it < 7; it++) {          // -> M^128
                double na = ma * ma + mb * mc;
                double nb = ma * mb + mb * md;
                double nc = mc * ma + md * mc;
                double nd = mc * mb + md * md;
                ma = na; mb = nb; mc = nc; md = nd;
            }
            for (int j = 0; j < NLVL; j++) {
                d_Pl[band][j][0] = (float)ma; d_Pl[band][j][1] = (float)mb;
                d_Pl[band][j][2] = (float)mc; d_Pl[band][j][3] = (float)md;
                double na = ma * ma + mb * mc;
                double nb = ma * mb + mb * md;
                double nc = mc * ma + md * mc;
                double nd = mc * mb + md * md;
                ma = na; mb = nb; mc = nc; md = nd;
            }
        }
    }
    __syncthreads();

    if (b == 0 && tid == 0 && write_scalars) {
        float sc = 0.f, smm = 0.f, spp = 0.f;
        for (int i = 0; i < BATCH; i++) { sc += s_lc[i]; smm += s_lm[i]; spp += s_lp[i]; }
        out_tail[0] = sc  / (float)BATCH;
        out_tail[1] = smm / (float)BATCH;
        out_tail[2] = spp / (float)BATCH;
    }

    KSParams P = sp;

    // load excitation into smem
    const float* xin = exc + b * NSMP;
    for (int i = tid; i < NSMP; i += NTH) sig[i] = xin[i];
    __syncthreads();

    // pre one-pole LP (input scaled by alpha*gain inside)
    lp_inplace(sig, scan, P.m_pre, P.sc_pre, tid);

    // Karplus-Strong (in-place). One barrier per chunk: with KSL=1024 the
    // chunk's ring writes never alias its reads (read distance Di+k in
    // [66,737]: Di+k > Cb and 1024-(Di+k) >= 287 > Cb). Only the warps that
    // own active lanes participate in the per-chunk barrier (bar.sync 1).
    {
        for (int i = tid; i < KSL; i += NTH) buf[i] = 0.f;
        __syncthreads();

        int   Di  = P.Di;
        float fr  = P.fr;
        float w1f = 1.f - fr;
        float gs  = P.gs, g1s = P.g1s;
        int Cb = min(NTH, Di - 2);
        if (Cb < 1) Cb = 1;
        int nwT = ((Cb + 31) >> 5) << 5;   // participating threads (whole warps)

        if (tid < nwT) {
            for (int base = 0; base < NSMP; base += Cb) {
                int  n   = base + tid;
                bool act = (tid < Cb) && (n < NSMP);
                if (act) {
                    int i1 = (n - Di     + 2048) & (KSL - 1);
                    int i2 = (n - Di - 1 + 2048) & (KSL - 1);
                    int i3 = (n - Di - 2 + 2048) & (KSL - 1);
                    float b1v = buf[i1], b2v = buf[i2], b3v = buf[i3];
                    float z  = fmaf(fr, b2v, w1f * b1v);
                    float z1 = fmaf(fr, b3v, w1f * b2v);
                    float y  = sig[n] + fmaf(gs, z1, g1s * z);
                    buf[n & (KSL - 1)] = y;
                    sig[n] = y;
                }
                asm volatile("bar.sync 1, %0;" :: "r"(nwT) : "memory");
            }
        }
        __syncthreads();
    }

    // post one-pole LP
    lp_inplace(sig, scan, P.m_post, P.sc_post, tid);

    // write string to global for body stage
    float* yout = d_scr + b * NSMP;
    for (int i = tid; i < NSMP; i += NTH) yout[i] = sig[i];
}

// ---------------------------------------------------------------------------
// Body pass A: per (chunk, batch) 1-warp block, lane = band.
// Zero-init serial BL-step 2-pole; store end state.
// ---------------------------------------------------------------------------
__global__ void bodyA_kernel()
{
    __shared__ float shx[BL];
    int b = blockIdx.y, c = blockIdx.x, tid = threadIdx.x;
    const float* x = d_scr + b * NSMP + c * BL;
    for (int i = tid; i < BL; i += 32) shx[i] = x[i];
    __syncthreads();
    if (tid < NB) {
        float a1 = d_bA1[tid], a2 = d_bA2[tid], b0 = d_bB0[tid];
        float y1 = 0.f, y2 = 0.f;
        #pragma unroll 8
        for (int t = 0; t < BL; t++) {
            float u = fmaf(-a2, y2, b0 * shx[t]);
            float y = fmaf(-a1, y1, u);
            y2 = y1; y1 = y;
        }
        d_carry[b][c][tid] = make_float2(y1, y2);
    }
}

// ---------------------------------------------------------------------------
// Body pass B: parallel affine scan of chunk carries.
// grid (NB, BATCH), BC threads. Level matrices are exact (double-computed in
// setup); scan only does float matvecs with them. Exclusive -> d_initS.
// ---------------------------------------------------------------------------
__global__ void bodyB_kernel()
{
    __shared__ float2 s[BC];
    int band = blockIdx.x, b = blockIdx.y, c = threadIdx.x;
    float2 v = d_carry[b][c][band];
    s[c] = v;
    __syncthreads();
    #pragma unroll
    for (int j = 0; j < NLVL; j++) {
        int ofs = 1 << j;
        float q00 = d_Pl[band][j][0], q01 = d_Pl[band][j][1];
        float q10 = d_Pl[band][j][2], q11 = d_Pl[band][j][3];
        float2 pv = (c >= ofs) ? s[c - ofs] : make_float2(0.f, 0.f);
        __syncthreads();
        v.x = fmaf(q00, pv.x, fmaf(q01, pv.y, v.x));
        v.y = fmaf(q10, pv.x, fmaf(q11, pv.y, v.y));
        s[c] = v;
        __syncthreads();
    }
    d_initS[b][c][band] = (c > 0) ? s[c - 1] : make_float2(0.f, 0.f);
}

// ---------------------------------------------------------------------------
// Body pass C: recompute with correct init, weighted band sum.
// ---------------------------------------------------------------------------
__global__ void bodyC_kernel(const float* __restrict__ gains, float* __restrict__ out)
{
    __shared__ float shx[BL];
    __shared__ float tile[BL * 25];   // [t][band], stride 25 (pad)
    __shared__ float shg[NB];
    int b = blockIdx.y, c = blockIdx.x, tid = threadIdx.x;
    const float* x = d_scr + b * NSMP + c * BL;
    for (int i = tid; i < BL; i += 32) shx[i] = x[i];
    if (tid < NB) shg[tid] = gains[tid];
    __syncthreads();

    if (tid < NB) {
        float a1 = d_bA1[tid], a2 = d_bA2[tid], b0 = d_bB0[tid];
        float2 s = d_initS[b][c][tid];
        float y1 = s.x, y2 = s.y;
        #pragma unroll 8
        for (int t = 0; t < BL; t++) {
            float u = fmaf(-a2, y2, b0 * shx[t]);
            float y = fmaf(-a1, y1, u);
            tile[t * 25 + tid] = y;
            y2 = y1; y1 = y;
        }
    }
    __syncthreads();

    for (int t = tid; t < BL; t += 32) {
        float acc = 0.f;
        #pragma unroll
        for (int k = 0; k < NB; k++) acc = fmaf(tile[t * 25 + k], shg[k], acc);
        out[b * NSMP + c * BL + t] = acc;
    }
}

// ---------------------------------------------------------------------------
extern "C" void kernel_launch(void* const* d_in, const int* in_sizes, int n_in,
                              void* d_out, int out_size)
{
    const float* exc   = (const float*)d_in[0];   // [8,1,32768]
    const float* pitch = (const float*)d_in[1];   // [8,1]
    const float* w1    = (const float*)d_in[2];   // [16,1]
    const float* b1    = (const float*)d_in[3];   // [16]
    const float* w2    = (const float*)d_in[4];   // [3,16]
    const float* b2    = (const float*)d_in[5];   // [3]
    const float* eg    = (const float*)d_in[6];   // scalar
    const float* bg    = (const float*)d_in[7];   // [1,24]
    float* out = (float*)d_out;

    int wr = (out_size >= BATCH * NSMP + 3) ? 1 : 0;

    const int smem_bytes = (NSMP + KSL + NTH) * (int)sizeof(float);  // ~136 KB
    cudaFuncSetAttribute(fused_kernel,
                         cudaFuncAttributeMaxDynamicSharedMemorySize, smem_bytes);

    fused_kernel<<<BATCH, NTH, smem_bytes>>>(exc, pitch, w1, b1, w2, b2, eg,
                                             out + BATCH * NSMP, wr);
    bodyA_kernel<<<dim3(BC, BATCH), 32>>>();
    bodyB_kernel<<<dim3(NB, BATCH), BC>>>();
    bodyC_kernel<<<dim3(BC, BATCH), 32>>>(bg, out);
}